// round 17
// baseline (speedup 1.0000x reference)
#include <cuda_runtime.h>
#include <cstdint>
#include <cstddef>

#define N_NODES 4096
#define IN_FEAT 256
#define N_HEADS 8
#define N_HIDDEN 32
#define OUT_FEAT 256   // N_HEADS * N_HIDDEN
#define JSPLIT 7
#define LOG2E 1.4426950408889634f

// Scratch (static __device__ globals: allocation-free per harness rules)
__device__ float d_si[N_NODES * N_HEADS];            // s_i[n][h] * log2(e)
__device__ float d_sj[N_NODES * N_HEADS];            // s_j[n][h] * log2(e)
__device__ unsigned d_gfrag[N_HEADS * 512 * 32 * 8]; // 4 MB: tf32 B-fragments
__device__ float d_part[JSPLIT][N_NODES * OUT_FEAT]; // 28 MB partial outputs
__device__ float d_rs[JSPLIT][N_NODES * N_HEADS];    // partial row sums

__device__ __forceinline__ unsigned cvt_tf32(float x) {
    unsigned r;
    asm("cvt.rna.tf32.f32 %0, %1;" : "=r"(r) : "f"(x));
    return r;
}
__device__ __forceinline__ float ex2(float x) {
    float r;
    asm("ex2.approx.f32 %0, %1;" : "=f"(r) : "f"(x));
    return r;
}
__device__ __forceinline__ void mma_tf32(float* c, unsigned a0, unsigned a1,
                                         unsigned a2, unsigned a3,
                                         unsigned b0, unsigned b1) {
    asm volatile(
        "mma.sync.aligned.m16n8k8.row.col.f32.tf32.tf32.f32 "
        "{%0,%1,%2,%3}, {%4,%5,%6,%7}, {%8,%9}, {%0,%1,%2,%3};"
        : "+f"(c[0]), "+f"(c[1]), "+f"(c[2]), "+f"(c[3])
        : "r"(a0), "r"(a1), "r"(a2), "r"(a3), "r"(b0), "r"(b1));
}

// ---------------------------------------------------------------------------
// Kernel 1 (fused, tensor-core, 512 threads) — EXACT R16 version (13.9us).
// g = h @ W^T for one (64-row, 2-head) tile via tf32 mma.m16n8k8, 16 warps
// with M16xN16 warp tiles. Epilogues: s_i/s_j from gS + shfl; fragment pack.
// ---------------------------------------------------------------------------
__global__ __launch_bounds__(512) void gemm_fused_kernel(const float* __restrict__ h,
                                                         const float* __restrict__ W,
                                                         const float* __restrict__ a) {
    __shared__ __align__(16) float buf[4608];    // As(64*36) + Bs(64*36); reused as gS(64*72)
    float* As = buf;            // [64][36] tf32 bits of h tile rows
    float* Bs = buf + 2304;     // [64][36] tf32 bits of W tile rows

    const int n0 = blockIdx.x * 64;
    const int by = blockIdx.y;               // head pair: heads 2by, 2by+1
    const int o0 = by * 64;
    const int t  = threadIdx.x;
    const int w  = t >> 5;       // 16 warps
    const int lane = t & 31;
    const int wr = w >> 2;       // 16-row block 0..3
    const int wc = w & 3;        // 16-col block 0..3
    const int gid = lane >> 2, tig = lane & 3;
    const int rstg = t >> 3;     // staging row 0..63
    const int c4s  = t & 7;      // staging float4-column

    float acc[2][4] = {};        // [nt][c0..c3]

    for (int ki = 0; ki < 8; ki++) {
        const int k0 = ki * 32;
        float4 av = *(const float4*)(h + (size_t)(n0 + rstg) * IN_FEAT + k0 + c4s * 4);
        float4 bv = *(const float4*)(W + (size_t)(o0 + rstg) * IN_FEAT + k0 + c4s * 4);
        __syncthreads();         // prior MMAs done before overwrite
        uint4 ua;
        ua.x = cvt_tf32(av.x); ua.y = cvt_tf32(av.y);
        ua.z = cvt_tf32(av.z); ua.w = cvt_tf32(av.w);
        *(uint4*)(As + rstg * 36 + c4s * 4) = ua;
        uint4 ub;
        ub.x = cvt_tf32(bv.x); ub.y = cvt_tf32(bv.y);
        ub.z = cvt_tf32(bv.z); ub.w = cvt_tf32(bv.w);
        *(uint4*)(Bs + rstg * 36 + c4s * 4) = ub;
        __syncthreads();

        const unsigned* Au = (const unsigned*)As;
        const unsigned* Bu = (const unsigned*)Bs;
        const int arow0 = (wr * 16 + gid) * 36;
        const int arow1 = arow0 + 8 * 36;
        const int brow  = (wc * 16 + gid) * 36;
#pragma unroll
        for (int ks = 0; ks < 4; ks++) {
            const int kk = ks * 8 + tig;
            unsigned a0 = Au[arow0 + kk];
            unsigned a1 = Au[arow1 + kk];
            unsigned a2 = Au[arow0 + kk + 4];
            unsigned a3 = Au[arow1 + kk + 4];
            mma_tf32(acc[0], a0, a1, a2, a3, Bu[brow + kk], Bu[brow + kk + 4]);
            mma_tf32(acc[1], a0, a1, a2, a3,
                     Bu[brow + 8 * 36 + kk], Bu[brow + 8 * 36 + kk + 4]);
        }
    }
    __syncthreads();             // all MMAs done before gS overwrites As/Bs

    // --- stage C to gS [64][72] ---
    float* gS = buf;
#pragma unroll
    for (int nt = 0; nt < 2; nt++) {
        int col = wc * 16 + nt * 8 + 2 * tig;
        int r0  = wr * 16 + gid;
        *(float2*)(gS + r0 * 72 + col)       = make_float2(acc[nt][0], acc[nt][1]);
        *(float2*)(gS + (r0 + 8) * 72 + col) = make_float2(acc[nt][2], acc[nt][3]);
    }
    __syncthreads();

    // --- epilogue A: s_i/s_j from gS ---
    {
        int r   = t >> 3;
        int sub = t & 7;
        int hd  = sub >> 2;
        int q   = sub & 3;
        const float* grow = gS + r * 72 + hd * 32 + q * 8;
        float si = 0.f, sj = 0.f;
#pragma unroll
        for (int j = 0; j < 8; j++) {
            float gv = grow[j];
            si = fmaf(gv, __ldg(a + q * 8 + j), si);
            sj = fmaf(gv, __ldg(a + 32 + q * 8 + j), sj);
        }
        si += __shfl_xor_sync(0xffffffffu, si, 1);
        si += __shfl_xor_sync(0xffffffffu, si, 2);
        sj += __shfl_xor_sync(0xffffffffu, sj, 1);
        sj += __shfl_xor_sync(0xffffffffu, sj, 2);
        if (q == 0) {
            int head = 2 * by + hd;
            d_si[(size_t)(n0 + r) * N_HEADS + head] = si * LOG2E;
            d_sj[(size_t)(n0 + r) * N_HEADS + head] = sj * LOG2E;
        }
    }

    // --- epilogue B: pack tf32 fragments (16 warps = 16 (hd,ktg) groups) ---
    {
        int hd  = w >> 3;
        int ktg = w & 7;
        unsigned v[8];
#pragma unroll
        for (int nt = 0; nt < 4; nt++)
#pragma unroll
            for (int half = 0; half < 2; half++)
                v[nt * 2 + half] = cvt_tf32(
                    gS[(ktg * 8 + half * 4 + tig) * 72 + hd * 32 + nt * 8 + gid]);
        size_t gt = ((size_t)(2 * by + hd) * 512 + (n0 >> 3) + ktg) * 32 + lane;
        uint4* dst = (uint4*)d_gfrag + gt * 2;
        dst[0] = make_uint4(v[0], v[1], v[2], v[3]);
        dst[1] = make_uint4(v[4], v[5], v[6], v[7]);
    }
}

// ---------------------------------------------------------------------------
// Kernel 2: attention — RESTRUCTURED: 16 i-rows per CTA (mt eliminated).
// Grid (256 i-tiles, JSPLIT) = 1792 CTAs, 256 threads = 8 warps (warp=head),
// launch_bounds(256,4): ~55 regs < 64 cap -> 4 CTAs/SM = 8 warps/SMSP.
// Halved per-kt dependency chain + doubled warps/SMSP hide the fragment LDG.
// Mask via arithmetic sign-mask + single LOP3 (bit-identical operands):
//   m = (int)(mrow << (31-bit)) >> 31;  a = bits(w) & m & 0xFFFFE000
// exp(lrelu(si+sj)) == max(Ei*Ej, Fi*Fj) (exact; no MUFU in hot loop).
// Arithmetic identical to R16 -> same rel_err expected.
// ---------------------------------------------------------------------------
__global__ __launch_bounds__(256, 4) void attn_kernel(const int* __restrict__ adj) {
    __shared__ float2 efS[N_HEADS * 64];   // (Ej, Fj) per [h][j_local]
    __shared__ unsigned adjLo[16];         // bits j0..j0+31 for 16 i-rows
    __shared__ unsigned adjHi[16];         // bits j0+32..j0+63

    const int i0   = blockIdx.x * 16;
    const int js   = blockIdx.y;           // 0..JSPLIT-1
    const int tid  = threadIdx.x;
    const int w    = tid >> 5;             // warp = head
    const int h    = w;
    const int lane = tid & 31;
    const int gid  = lane >> 2;
    const int tig  = lane & 3;

    float Ei0, Fi0, Ei1, Fi1;
    {
        float s0 = d_si[(size_t)(i0 + gid) * N_HEADS + h];
        float s1 = d_si[(size_t)(i0 + 8 + gid) * N_HEADS + h];
        Ei0 = ex2(s0); Fi0 = ex2(0.2f * s0);
        Ei1 = ex2(s1); Fi1 = ex2(0.2f * s1);
    }

    float acc[4][4] = {};
    float rs0 = 0.f, rs1 = 0.f;

    const uint4* fragbase = (const uint4*)d_gfrag + (size_t)h * 512 * 32 * 2;

    for (int jt = js; jt < 64; jt += JSPLIT) {
        const int j0 = jt * 64;
        __syncthreads();
        // stage (Ej, Fj) tile: 512 pairs, 2 reps, coalesced d_sj read
#pragma unroll
        for (int rep = 0; rep < 2; rep++) {
            int idx = tid + rep * 256;
            int jl = idx >> 3, hh = idx & 7;
            float sj = d_sj[(size_t)(j0 + jl) * N_HEADS + hh];
            efS[hh * 64 + jl] = make_float2(ex2(sj), ex2(0.2f * sj));
        }
        // adjacency -> bitmasks via ballot (warp w stages rows 2w, 2w+1)
#pragma unroll
        for (int rr = 0; rr < 2; rr++) {
            int r = w * 2 + rr;
            const int* arow = adj + (size_t)(i0 + r) * N_NODES + j0;
            unsigned b0 = __ballot_sync(0xffffffffu, arow[lane] != 0);
            unsigned b1 = __ballot_sync(0xffffffffu, arow[32 + lane] != 0);
            if (lane == 0) { adjLo[r] = b0; adjHi[r] = b1; }
        }
        __syncthreads();

        unsigned mrow0, mrow1;
#pragma unroll
        for (int kt = 0; kt < 8; kt++) {
            if (kt == 0) { mrow0 = adjLo[gid]; mrow1 = adjLo[8 + gid]; }
            if (kt == 4) { mrow0 = adjHi[gid]; mrow1 = adjHi[8 + gid]; }

            const uint4* fb = fragbase + ((size_t)(jt * 8 + kt) * 32 + lane) * 2;
            uint4 q0 = __ldg(fb);
            uint4 q1 = __ldg(fb + 1);
            float2 ef0 = efS[h * 64 + kt * 8 + tig];
            float2 ef1 = efS[h * 64 + kt * 8 + tig + 4];
            const int shA = 31 - (kt & 3) * 8 - tig;   // col tig bit -> bit 31
            const int shB = shA - 4;                   // col tig+4 bit -> bit 31

            unsigned m00 = (unsigned)((int)(mrow0 << shA) >> 31);
            unsigned m01 = (unsigned)((int)(mrow0 << shB) >> 31);
            unsigned m10 = (unsigned)((int)(mrow1 << shA) >> 31);
            unsigned m11 = (unsigned)((int)(mrow1 << shB) >> 31);

            float w00 = fmaxf(Ei0 * ef0.x, Fi0 * ef0.y);
            float w01 = fmaxf(Ei0 * ef1.x, Fi0 * ef1.y);
            float w10 = fmaxf(Ei1 * ef0.x, Fi1 * ef0.y);
            float w11 = fmaxf(Ei1 * ef1.x, Fi1 * ef1.y);

            unsigned a0 = __float_as_uint(w00) & m00 & 0xFFFFE000u;  // one LOP3
            unsigned a2 = __float_as_uint(w01) & m01 & 0xFFFFE000u;
            unsigned a1 = __float_as_uint(w10) & m10 & 0xFFFFE000u;
            unsigned a3 = __float_as_uint(w11) & m11 & 0xFFFFE000u;

            rs0 += __uint_as_float(a0) + __uint_as_float(a2);
            rs1 += __uint_as_float(a1) + __uint_as_float(a3);

            mma_tf32(acc[0], a0, a1, a2, a3, q0.x, q0.y);
            mma_tf32(acc[1], a0, a1, a2, a3, q0.z, q0.w);
            mma_tf32(acc[2], a0, a1, a2, a3, q1.x, q1.y);
            mma_tf32(acc[3], a0, a1, a2, a3, q1.z, q1.w);
        }
    }

    // reduce row sums across the 4 tig lanes sharing each row
    rs0 += __shfl_xor_sync(0xffffffffu, rs0, 1);
    rs0 += __shfl_xor_sync(0xffffffffu, rs0, 2);
    rs1 += __shfl_xor_sync(0xffffffffu, rs1, 1);
    rs1 += __shfl_xor_sync(0xffffffffu, rs1, 2);
    if (tig == 0) {
        d_rs[js][(size_t)(i0 + gid) * N_HEADS + h]     = rs0;
        d_rs[js][(size_t)(i0 + 8 + gid) * N_HEADS + h] = rs1;
    }
    // partial (unnormalized) output
    {
        int r0 = i0 + gid;
        int r1 = r0 + 8;
#pragma unroll
        for (int nt = 0; nt < 4; nt++) {
            int c = h * N_HIDDEN + nt * 8 + tig * 2;
            *(float2*)(&d_part[js][(size_t)r0 * OUT_FEAT + c]) =
                make_float2(acc[nt][0], acc[nt][1]);
            *(float2*)(&d_part[js][(size_t)r1 * OUT_FEAT + c]) =
                make_float2(acc[nt][2], acc[nt][3]);
        }
    }
}

// ---------------------------------------------------------------------------
// Kernel 3: reduce partials and normalize (unchanged).
// ---------------------------------------------------------------------------
__global__ __launch_bounds__(256) void reduce_kernel(float* __restrict__ out) {
    int t  = blockIdx.x * 256 + threadIdx.x;   // 0..262143
    int i  = t >> 6;
    int c4 = t & 63;
    int hh = c4 >> 3;

    float4 num = make_float4(0.f, 0.f, 0.f, 0.f);
    float den = 0.f;
#pragma unroll
    for (int s = 0; s < JSPLIT; s++) {
        float4 p = *(const float4*)(&d_part[s][(size_t)i * OUT_FEAT + c4 * 4]);
        num.x += p.x; num.y += p.y; num.z += p.z; num.w += p.w;
        den += d_rs[s][(size_t)i * N_HEADS + hh];
    }
    float inv = 1.0f / den;
    *(float4*)(out + (size_t)i * OUT_FEAT + c4 * 4) =
        make_float4(num.x * inv, num.y * inv, num.z * inv, num.w * inv);
}

// ---------------------------------------------------------------------------
// Launch
// ---------------------------------------------------------------------------
extern "C" void kernel_launch(void* const* d_in, const int* in_sizes, int n_in,
                              void* d_out, int out_size) {
    const float* h   = (const float*)d_in[0];   // [4096, 256]
    const float* W   = (const float*)d_in[1];   // [256, 256]
    const float* a   = (const float*)d_in[2];   // [64]
    const int*   adj = (const int*)d_in[3];     // [4096, 4096, 1]
    float* out = (float*)d_out;                 // [4096, 256]

    (void)in_sizes; (void)n_in; (void)out_size;

    dim3 g1(N_NODES / 64, N_HEADS / 2);
    gemm_fused_kernel<<<g1, 512>>>(h, W, a);

    attn_kernel<<<dim3(N_NODES / 16, JSPLIT), 256>>>(adj);

    reduce_kernel<<<(N_NODES * OUT_FEAT / 4) / 256, 256>>>(out);
}